// round 1
// baseline (speedup 1.0000x reference)
#include <cuda_runtime.h>
#include <cstdint>
#include <cstddef>

// ---------------- problem constants ----------------
constexpr int QL     = 1024;   // qlen = klen = rlen
constexpr int BS     = 4;      // batch
constexpr int DMODEL = 1024;
constexpr int NHEAD  = 16;
constexpr int DHEAD  = 64;
constexpr int NROWS  = QL * BS;          // 4096 flattened (i,b) rows
constexpr int HCOLS  = 3 * NHEAD * DHEAD; // 3072
constexpr float SCALE = 0.125f;          // 1/sqrt(64)
constexpr float LNEPS = 1e-5f;

// ---------------- scratch (device globals; no allocation allowed) ----------------
__device__ float g_heads[(size_t)NROWS * HCOLS];   // q|k|v heads, 48MB
__device__ float g_rk[(size_t)QL * DMODEL];        // r @ r_w
__device__ float g_biask[BS * NHEAD * QL];         // r_w_bias . k
__device__ float g_biasr[NHEAD * QL];              // r_r_bias . r_k
__device__ float g_vec[(size_t)NROWS * DMODEL];    // attention output
__device__ float g_proj[(size_t)NROWS * DMODEL];   // vec @ o_w

// ---------------- generic 64x64 tile SGEMM (C = A[M,K] @ B[K,N]) ----------------
__global__ __launch_bounds__(256) void sgemm64(const float* __restrict__ A,
                                               const float* __restrict__ B,
                                               float* __restrict__ C,
                                               int M, int N, int K) {
    __shared__ float a_s[16][65];   // [k][row]
    __shared__ float b_s[16][65];   // [k][col]
    const int t  = threadIdx.x;
    const int tx = t & 15, ty = t >> 4;
    const int row0 = blockIdx.y * 64, col0 = blockIdx.x * 64;
    float acc[4][4] = {};

    for (int k0 = 0; k0 < K; k0 += 16) {
        #pragma unroll
        for (int i = 0; i < 4; i++) {
            int e = t + 256 * i;
            int r  = e >> 4, kk = e & 15;           // A tile: 64 rows x 16 k
            a_s[kk][r] = A[(size_t)(row0 + r) * K + k0 + kk];
            int k2 = e >> 6, c = e & 63;            // B tile: 16 k x 64 cols
            b_s[k2][c] = B[(size_t)(k0 + k2) * N + col0 + c];
        }
        __syncthreads();
        #pragma unroll
        for (int kk = 0; kk < 16; kk++) {
            float av[4], bv[4];
            #pragma unroll
            for (int a = 0; a < 4; a++)  av[a] = a_s[kk][ty * 4 + a];
            #pragma unroll
            for (int b2 = 0; b2 < 4; b2++) bv[b2] = b_s[kk][tx * 4 + b2];
            #pragma unroll
            for (int a = 0; a < 4; a++)
                #pragma unroll
                for (int b2 = 0; b2 < 4; b2++)
                    acc[a][b2] += av[a] * bv[b2];
        }
        __syncthreads();
    }
    #pragma unroll
    for (int a = 0; a < 4; a++)
        #pragma unroll
        for (int b2 = 0; b2 < 4; b2++)
            C[(size_t)(row0 + ty * 4 + a) * N + col0 + tx * 4 + b2] = acc[a][b2];
}

// ---------------- bias precompute: biask[b][h][j] = rwb[h] . k_h[j,b,h,:] ----------------
__global__ __launch_bounds__(256) void bias_k_kernel(const float* __restrict__ heads,
                                                     const float* __restrict__ rwb,
                                                     float* __restrict__ bk) {
    int gt = blockIdx.x * 256 + threadIdx.x;
    int wi = gt >> 5, lane = gt & 31;          // wi in [0, 65536)
    int j = wi & (QL - 1);
    int bh = wi >> 10;
    int b = bh >> 4, h = bh & 15;
    const float* kp = heads + ((size_t)j * BS + b) * HCOLS + 1024 + h * 64;
    const float* wp = rwb + h * 64;
    float s = kp[lane] * wp[lane] + kp[lane + 32] * wp[lane + 32];
    #pragma unroll
    for (int o = 16; o; o >>= 1) s += __shfl_xor_sync(0xffffffffu, s, o);
    if (lane == 0) bk[wi] = s;
}

// biasr[h][m] = rrb[h] . r_k[m,h,:]
__global__ __launch_bounds__(256) void bias_r_kernel(const float* __restrict__ rk,
                                                     const float* __restrict__ rrb,
                                                     float* __restrict__ brv) {
    int gt = blockIdx.x * 256 + threadIdx.x;
    int wi = gt >> 5, lane = gt & 31;          // wi in [0, 16384)
    int m = wi & (QL - 1);
    int h = wi >> 10;
    const float* rp = rk + (size_t)m * DMODEL + h * 64;
    const float* wp = rrb + h * 64;
    float s = rp[lane] * wp[lane] + rp[lane + 32] * wp[lane + 32];
    #pragma unroll
    for (int o = 16; o; o >>= 1) s += __shfl_xor_sync(0xffffffffu, s, o);
    if (lane == 0) brv[wi] = s;
}

// ---------------- fused causal rel-attention (flash-style, 64x64 tiles) ----------------
// S[i,j] = scale*( q_i.(k_j + rk[1023-i+j]) + biask[j] + biasr[1023-i+j] ), j<=i
constexpr int ATTN_SMEM_FLOATS = 4 * 64 * 65 + 64 * 129 + 128 + 64;
constexpr int ATTN_SMEM_BYTES  = ATTN_SMEM_FLOATS * 4;

__global__ __launch_bounds__(256) void attn_kernel(const float* __restrict__ heads,
                                                   const float* __restrict__ rk,
                                                   const float* __restrict__ biask,
                                                   const float* __restrict__ biasr,
                                                   float* __restrict__ vec) {
    extern __shared__ float sm[];
    float* q_s  = sm;                 // [64][65]  d-major: q_s[d*65+ii]
    float* k_s  = q_s + 64 * 65;      // [64][65]  d-major: k_s[d*65+jj]
    float* v_s  = k_s + 64 * 65;      // [64][65]  jj-major: v_s[jj*65+d]
    float* s_s  = v_s + 64 * 65;      // [64][65]  prob tile, row-major
    float* rk_s = s_s + 64 * 65;      // [64][129] d-major band: rk_s[d*129+c]
    float* brs  = rk_s + 64 * 129;    // [128] biasr band
    float* bks  = brs + 128;          // [64]  biask cols

    const int bh = blockIdx.x;                   // 0..63
    const int b = bh >> 4, h = bh & 15;
    const int ib = (int)gridDim.y - 1 - (int)blockIdx.y;   // long blocks first
    const int i0 = ib * 64;
    const int t = threadIdx.x;
    const int tx = t & 15, ty = t >> 4;
    const int cbase = 63 + tx * 4 - ty * 4;      // band col for (a=0,b2=0)

    // Q tile (raw q heads)
    for (int e = t; e < 64 * 64; e += 256) {
        int ii = e >> 6, d = e & 63;
        q_s[d * 65 + ii] = heads[((size_t)(i0 + ii) * BS + b) * HCOLS + h * 64 + d];
    }

    float m_run[4], l_run[4], o_acc[4][4];
    #pragma unroll
    for (int a = 0; a < 4; a++) {
        m_run[a] = -1e30f; l_run[a] = 0.f;
        #pragma unroll
        for (int b2 = 0; b2 < 4; b2++) o_acc[a][b2] = 0.f;
    }

    const float* bk = biask + (size_t)(b * NHEAD + h) * QL;
    const float* br = biasr + (size_t)h * QL;

    for (int jt = 0; jt <= ib; jt++) {
        const int j0 = jt * 64;
        __syncthreads();   // previous tile's s_s / v_s reads done

        for (int e = t; e < 64 * 64; e += 256) {
            int jj = e >> 6, d = e & 63;
            size_t base = ((size_t)(j0 + jj) * BS + b) * HCOLS + h * 64 + d;
            k_s[d * 65 + jj] = heads[base + 1024];
            v_s[jj * 65 + d] = heads[base + 2048];
        }
        const int mlo = QL - 64 - i0 + j0;       // band start (>= 0 always)
        for (int e = t; e < 128 * 64; e += 256) {
            int c = e >> 6, d = e & 63;
            int msrc = mlo + c; if (msrc > QL - 1) msrc = QL - 1;  // clamp (masked)
            rk_s[d * 129 + c] = rk[(size_t)msrc * DMODEL + h * 64 + d];
        }
        if (t < 128) {
            int msrc = mlo + t; if (msrc > QL - 1) msrc = QL - 1;
            brs[t] = br[msrc];
        } else if (t < 192) {
            bks[t - 128] = bk[j0 + (t - 128)];
        }
        __syncthreads();

        // ---- fused AC+BD score tile ----
        float acc[4][4] = {};
        #pragma unroll 4
        for (int d = 0; d < 64; d++) {
            float qv[4], kv[4], rv[7];
            #pragma unroll
            for (int a = 0; a < 4; a++)  qv[a] = q_s[d * 65 + ty * 4 + a];
            #pragma unroll
            for (int b2 = 0; b2 < 4; b2++) kv[b2] = k_s[d * 65 + tx * 4 + b2];
            #pragma unroll
            for (int u = 0; u < 7; u++)  rv[u] = rk_s[d * 129 + cbase - 3 + u];
            #pragma unroll
            for (int a = 0; a < 4; a++)
                #pragma unroll
                for (int b2 = 0; b2 < 4; b2++)
                    acc[a][b2] += qv[a] * (kv[b2] + rv[b2 - a + 3]);
        }

        // ---- biases + scale + causal mask ----
        float brow[7], bcol[4];
        #pragma unroll
        for (int u = 0; u < 7; u++) brow[u] = brs[cbase - 3 + u];
        #pragma unroll
        for (int b2 = 0; b2 < 4; b2++) bcol[b2] = bks[tx * 4 + b2];
        #pragma unroll
        for (int a = 0; a < 4; a++)
            #pragma unroll
            for (int b2 = 0; b2 < 4; b2++) {
                float sc = (acc[a][b2] + bcol[b2] + brow[b2 - a + 3]) * SCALE;
                if (j0 + tx * 4 + b2 > i0 + ty * 4 + a) sc = -1e30f;
                acc[a][b2] = sc;
            }

        // ---- online softmax (rows distributed over 16-lane tx groups) ----
        #pragma unroll
        for (int a = 0; a < 4; a++) {
            float mx = fmaxf(fmaxf(acc[a][0], acc[a][1]), fmaxf(acc[a][2], acc[a][3]));
            #pragma unroll
            for (int o = 8; o; o >>= 1) mx = fmaxf(mx, __shfl_xor_sync(0xffffffffu, mx, o));
            float mnew = fmaxf(m_run[a], mx);
            float corr = __expf(m_run[a] - mnew);
            float rs = 0.f;
            #pragma unroll
            for (int b2 = 0; b2 < 4; b2++) {
                float p = __expf(acc[a][b2] - mnew);
                acc[a][b2] = p; rs += p;
            }
            #pragma unroll
            for (int o = 8; o; o >>= 1) rs += __shfl_xor_sync(0xffffffffu, rs, o);
            l_run[a] = l_run[a] * corr + rs;
            m_run[a] = mnew;
            #pragma unroll
            for (int b2 = 0; b2 < 4; b2++) o_acc[a][b2] *= corr;
        }

        // ---- P @ V ----
        #pragma unroll
        for (int a = 0; a < 4; a++)
            #pragma unroll
            for (int b2 = 0; b2 < 4; b2++)
                s_s[(ty * 4 + a) * 65 + tx * 4 + b2] = acc[a][b2];
        __syncthreads();
        #pragma unroll 4
        for (int jj = 0; jj < 64; jj++) {
            float pv[4], vv[4];
            #pragma unroll
            for (int a = 0; a < 4; a++)  pv[a] = s_s[(ty * 4 + a) * 65 + jj];
            #pragma unroll
            for (int b2 = 0; b2 < 4; b2++) vv[b2] = v_s[jj * 65 + tx * 4 + b2];
            #pragma unroll
            for (int a = 0; a < 4; a++)
                #pragma unroll
                for (int b2 = 0; b2 < 4; b2++)
                    o_acc[a][b2] += pv[a] * vv[b2];
        }
    }

    #pragma unroll
    for (int a = 0; a < 4; a++) {
        float inv = 1.f / l_run[a];
        #pragma unroll
        for (int b2 = 0; b2 < 4; b2++)
            vec[((size_t)(i0 + ty * 4 + a) * BS + b) * DMODEL + h * 64 + tx * 4 + b2] =
                o_acc[a][b2] * inv;
    }
}

// ---------------- residual + layernorm ----------------
__global__ __launch_bounds__(256) void ln_kernel(const float* __restrict__ w,
                                                 const float* __restrict__ proj,
                                                 const float* __restrict__ g,
                                                 const float* __restrict__ bta,
                                                 float* __restrict__ out) {
    __shared__ float red[8];
    const int row = blockIdx.x;
    const int t = threadIdx.x;
    const size_t base = (size_t)row * DMODEL;
    float x[4];
    float s = 0.f;
    #pragma unroll
    for (int u = 0; u < 4; u++) {
        int c = t + u * 256;
        x[u] = w[base + c] + proj[base + c];
        s += x[u];
    }
    #pragma unroll
    for (int o = 16; o; o >>= 1) s += __shfl_xor_sync(0xffffffffu, s, o);
    if ((t & 31) == 0) red[t >> 5] = s;
    __syncthreads();
    float tot = 0.f;
    #pragma unroll
    for (int i = 0; i < 8; i++) tot += red[i];
    const float mu = tot * (1.f / DMODEL);

    float vs = 0.f;
    #pragma unroll
    for (int u = 0; u < 4; u++) { float dd = x[u] - mu; vs += dd * dd; }
    #pragma unroll
    for (int o = 16; o; o >>= 1) vs += __shfl_xor_sync(0xffffffffu, vs, o);
    __syncthreads();
    if ((t & 31) == 0) red[t >> 5] = vs;
    __syncthreads();
    tot = 0.f;
    #pragma unroll
    for (int i = 0; i < 8; i++) tot += red[i];
    const float rstd = rsqrtf(tot * (1.f / DMODEL) + LNEPS);

    #pragma unroll
    for (int u = 0; u < 4; u++) {
        int c = t + u * 256;
        out[base + c] = (x[u] - mu) * rstd * g[c] + bta[c];
    }
}

// ---------------- launch ----------------
extern "C" void kernel_launch(void* const* d_in, const int* in_sizes, int n_in,
                              void* d_out, int out_size) {
    const float* w    = (const float*)d_in[0];
    const float* r    = (const float*)d_in[1];
    // d_in[2] = attn_mask: deterministic causal triu(k=1); enforced in-kernel.
    const float* qkvw = (const float*)d_in[3];
    const float* rw   = (const float*)d_in[4];
    const float* ow   = (const float*)d_in[5];
    const float* rrb  = (const float*)d_in[6];
    const float* rwb  = (const float*)d_in[7];
    const float* lng  = (const float*)d_in[8];
    const float* lnb  = (const float*)d_in[9];
    float* out = (float*)d_out;

    float *heads, *rkbuf, *bk, *brv, *vec, *proj;
    cudaGetSymbolAddress((void**)&heads, g_heads);
    cudaGetSymbolAddress((void**)&rkbuf, g_rk);
    cudaGetSymbolAddress((void**)&bk,    g_biask);
    cudaGetSymbolAddress((void**)&brv,   g_biasr);
    cudaGetSymbolAddress((void**)&vec,   g_vec);
    cudaGetSymbolAddress((void**)&proj,  g_proj);

    cudaFuncSetAttribute(attn_kernel, cudaFuncAttributeMaxDynamicSharedMemorySize,
                         ATTN_SMEM_BYTES);

    // 1) heads = w @ qkv_w   [4096 x 3072 x 1024]
    sgemm64<<<dim3(HCOLS / 64, NROWS / 64), 256>>>(w, qkvw, heads, NROWS, HCOLS, DMODEL);
    // 2) r_k = r @ r_w       [1024 x 1024 x 1024]
    sgemm64<<<dim3(DMODEL / 64, QL / 64), 256>>>(r, rw, rkbuf, QL, DMODEL, DMODEL);
    // 3) bias terms
    bias_k_kernel<<<(BS * NHEAD * QL * 32) / 256, 256>>>(heads, rwb, bk);
    bias_r_kernel<<<(NHEAD * QL * 32) / 256, 256>>>(rkbuf, rrb, brv);
    // 4) attention
    attn_kernel<<<dim3(BS * NHEAD, QL / 64), 256, ATTN_SMEM_BYTES>>>(heads, rkbuf, bk, brv, vec);
    // 5) proj = vec @ o_w    [4096 x 1024 x 1024]
    sgemm64<<<dim3(DMODEL / 64, NROWS / 64), 256>>>(vec, ow, proj, NROWS, DMODEL, DMODEL);
    // 6) out = LN(w + proj)
    ln_kernel<<<NROWS, 256>>>(w, proj, lng, lnb, out);
}

// round 3
// speedup vs baseline: 2.0562x; 2.0562x over previous
#include <cuda_runtime.h>
#include <cstdint>
#include <cstddef>

// ---------------- problem constants ----------------
constexpr int QL     = 1024;
constexpr int BS     = 4;
constexpr int DMODEL = 1024;
constexpr int NHEAD  = 16;
constexpr int NROWS  = QL * BS;           // 4096
constexpr int HCOLS  = 3 * NHEAD * 64;    // 3072
constexpr float SCALE = 0.125f;
constexpr float LNEPS = 1e-5f;

// ---------------- scratch ----------------
__device__ float g_heads[(size_t)NROWS * HCOLS];
__device__ float g_rk[(size_t)QL * DMODEL];
__device__ float g_biask[BS * NHEAD * QL];
__device__ float g_biasr[NHEAD * QL];
__device__ float g_vec[(size_t)NROWS * DMODEL];
__device__ float g_proj[(size_t)NROWS * DMODEL];
__device__ float g_qkvT[(size_t)HCOLS * DMODEL];   // qkv_w^T [N,K]
__device__ float g_rwT[(size_t)DMODEL * DMODEL];
__device__ float g_owT[(size_t)DMODEL * DMODEL];

__device__ __forceinline__ float tf32r(float x) {
    float y;
    asm("cvt.rna.tf32.f32 %0, %1;" : "=f"(y) : "f"(x));
    return y;
}
__device__ __forceinline__ void mma_tf32(float* d, const uint32_t* a, const uint32_t* b) {
    asm volatile(
        "mma.sync.aligned.m16n8k8.row.col.f32.tf32.tf32.f32 "
        "{%0,%1,%2,%3}, {%4,%5,%6,%7}, {%8,%9}, {%0,%1,%2,%3};\n"
        : "+f"(d[0]), "+f"(d[1]), "+f"(d[2]), "+f"(d[3])
        : "r"(a[0]), "r"(a[1]), "r"(a[2]), "r"(a[3]), "r"(b[0]), "r"(b[1]));
}

// ---------------- weight transpose: out[n][k] = in[k][n] ----------------
__global__ __launch_bounds__(256) void transpose_k(const float* __restrict__ in,
                                                   float* __restrict__ out,
                                                   int K, int N) {
    __shared__ float t[32][33];
    int n0 = blockIdx.x * 32, k0 = blockIdx.y * 32;
    int tx = threadIdx.x, ty = threadIdx.y;
    #pragma unroll
    for (int i = 0; i < 32; i += 8)
        t[ty + i][tx] = in[(size_t)(k0 + ty + i) * N + n0 + tx];
    __syncthreads();
    #pragma unroll
    for (int i = 0; i < 32; i += 8)
        out[(size_t)(n0 + ty + i) * K + k0 + tx] = t[tx][ty + i];
}

// ---------------- mma.sync tf32 GEMM: C[M,N] = A[M,K] @ BT[N,K]^T ----------------
// CTA 128x128, 8 warps in 2x4 grid, warp tile 64x32, K-chunk 32, single-buffered SMEM.
constexpr int KC = 32;
constexpr int SM_PITCH = 36;          // floats per row (pad: 144B = 9*16B, conflict-free)

__global__ __launch_bounds__(256)
void gemm_tf32(const float* __restrict__ A, const float* __restrict__ BT,
               float* __restrict__ C, int M, int N, int K) {
    __shared__ float a_s[128 * SM_PITCH];
    __shared__ float b_s[128 * SM_PITCH];

    const int t = threadIdx.x;
    const int wid = t >> 5, lane = t & 31;
    const int wr = wid >> 2, wc = wid & 3;            // warp row/col in CTA tile
    const int qrow = lane >> 2, qcol = lane & 3;
    const int row0 = blockIdx.y * 128, col0 = blockIdx.x * 128;

    float acc[4][4][4] = {};

    for (int k0 = 0; k0 < K; k0 += KC) {
        __syncthreads();
        // load A[row0..+128][k0..+32] and BT[col0..+128][k0..+32] (float4, tf32-rounded)
        #pragma unroll
        for (int i = 0; i < 4; i++) {
            int idx = t + i * 256;                    // 0..1023 float4s
            int rr = idx >> 3, kq = (idx & 7) * 4;
            float4 va = *(const float4*)&A[(size_t)(row0 + rr) * K + k0 + kq];
            va.x = tf32r(va.x); va.y = tf32r(va.y); va.z = tf32r(va.z); va.w = tf32r(va.w);
            *(float4*)&a_s[rr * SM_PITCH + kq] = va;
            float4 vb = *(const float4*)&BT[(size_t)(col0 + rr) * K + k0 + kq];
            vb.x = tf32r(vb.x); vb.y = tf32r(vb.y); vb.z = tf32r(vb.z); vb.w = tf32r(vb.w);
            *(float4*)&b_s[rr * SM_PITCH + kq] = vb;
        }
        __syncthreads();

        #pragma unroll
        for (int ks = 0; ks < KC / 8; ks++) {
            const int kk = ks * 8;
            uint32_t af[4][4], bf[4][2];
            #pragma unroll
            for (int mt = 0; mt < 4; mt++) {
                const int r0 = wr * 64 + mt * 16 + qrow;
                af[mt][0] = __float_as_uint(a_s[r0 * SM_PITCH + kk + qcol]);
                af[mt][1] = __float_as_uint(a_s[(r0 + 8) * SM_PITCH + kk + qcol]);
                af[mt][2] = __float_as_uint(a_s[r0 * SM_PITCH + kk + qcol + 4]);
                af[mt][3] = __float_as_uint(a_s[(r0 + 8) * SM_PITCH + kk + qcol + 4]);
            }
            #pragma unroll
            for (int nt = 0; nt < 4; nt++) {
                const int n0 = wc * 32 + nt * 8 + qrow;
                bf[nt][0] = __float_as_uint(b_s[n0 * SM_PITCH + kk + qcol]);
                bf[nt][1] = __float_as_uint(b_s[n0 * SM_PITCH + kk + qcol + 4]);
            }
            #pragma unroll
            for (int mt = 0; mt < 4; mt++)
                #pragma unroll
                for (int nt = 0; nt < 4; nt++)
                    mma_tf32(acc[mt][nt], af[mt], bf[nt]);
        }
    }

    // epilogue: float2 stores
    #pragma unroll
    for (int mt = 0; mt < 4; mt++) {
        const int row = row0 + wr * 64 + mt * 16 + qrow;
        #pragma unroll
        for (int nt = 0; nt < 4; nt++) {
            const int col = col0 + wc * 32 + nt * 8 + qcol * 2;
            *(float2*)&C[(size_t)row * N + col] = make_float2(acc[mt][nt][0], acc[mt][nt][1]);
            *(float2*)&C[(size_t)(row + 8) * N + col] = make_float2(acc[mt][nt][2], acc[mt][nt][3]);
        }
    }
}

// ---------------- bias precompute ----------------
__global__ __launch_bounds__(256) void bias_k_kernel(const float* __restrict__ heads,
                                                     const float* __restrict__ rwb,
                                                     float* __restrict__ bk) {
    int gt = blockIdx.x * 256 + threadIdx.x;
    int wi = gt >> 5, lane = gt & 31;
    int j = wi & (QL - 1);
    int bh = wi >> 10;
    int b = bh >> 4, h = bh & 15;
    const float* kp = heads + ((size_t)j * BS + b) * HCOLS + 1024 + h * 64;
    const float* wp = rwb + h * 64;
    float s = kp[lane] * wp[lane] + kp[lane + 32] * wp[lane + 32];
    #pragma unroll
    for (int o = 16; o; o >>= 1) s += __shfl_xor_sync(0xffffffffu, s, o);
    if (lane == 0) bk[wi] = s;
}
__global__ __launch_bounds__(256) void bias_r_kernel(const float* __restrict__ rk,
                                                     const float* __restrict__ rrb,
                                                     float* __restrict__ brv) {
    int gt = blockIdx.x * 256 + threadIdx.x;
    int wi = gt >> 5, lane = gt & 31;
    int m = wi & (QL - 1);
    int h = wi >> 10;
    const float* rp = rk + (size_t)m * DMODEL + h * 64;
    const float* wp = rrb + h * 64;
    float s = rp[lane] * wp[lane] + rp[lane + 32] * wp[lane + 32];
    #pragma unroll
    for (int o = 16; o; o >>= 1) s += __shfl_xor_sync(0xffffffffu, s, o);
    if (lane == 0) brv[wi] = s;
}

// ---------------- fused causal rel-attention (fp32 flash-style, 64x64 tiles) ----------------
constexpr int ATTN_SMEM_FLOATS = 4 * 64 * 65 + 64 * 129 + 128 + 64;
constexpr int ATTN_SMEM_BYTES  = ATTN_SMEM_FLOATS * 4;

__global__ __launch_bounds__(256) void attn_kernel(const float* __restrict__ heads,
                                                   const float* __restrict__ rk,
                                                   const float* __restrict__ biask,
                                                   const float* __restrict__ biasr,
                                                   float* __restrict__ vec) {
    extern __shared__ float sm[];
    float* q_s  = sm;
    float* k_s  = q_s + 64 * 65;
    float* v_s  = k_s + 64 * 65;
    float* s_s  = v_s + 64 * 65;
    float* rk_s = s_s + 64 * 65;
    float* brs  = rk_s + 64 * 129;
    float* bks  = brs + 128;

    const int bh = blockIdx.x;
    const int b = bh >> 4, h = bh & 15;
    const int ib = (int)gridDim.y - 1 - (int)blockIdx.y;
    const int i0 = ib * 64;
    const int t = threadIdx.x;
    const int tx = t & 15, ty = t >> 4;
    const int cbase = 63 + tx * 4 - ty * 4;

    for (int e = t; e < 64 * 64; e += 256) {
        int ii = e >> 6, d = e & 63;
        q_s[d * 65 + ii] = heads[((size_t)(i0 + ii) * BS + b) * HCOLS + h * 64 + d];
    }

    float m_run[4], l_run[4], o_acc[4][4];
    #pragma unroll
    for (int a = 0; a < 4; a++) {
        m_run[a] = -1e30f; l_run[a] = 0.f;
        #pragma unroll
        for (int b2 = 0; b2 < 4; b2++) o_acc[a][b2] = 0.f;
    }

    const float* bk = biask + (size_t)(b * NHEAD + h) * QL;
    const float* br = biasr + (size_t)h * QL;

    for (int jt = 0; jt <= ib; jt++) {
        const int j0 = jt * 64;
        __syncthreads();
        for (int e = t; e < 64 * 64; e += 256) {
            int jj = e >> 6, d = e & 63;
            size_t bas = ((size_t)(j0 + jj) * BS + b) * HCOLS + h * 64 + d;
            k_s[d * 65 + jj] = heads[bas + 1024];
            v_s[jj * 65 + d] = heads[bas + 2048];
        }
        const int mlo = QL - 64 - i0 + j0;
        for (int e = t; e < 128 * 64; e += 256) {
            int c = e >> 6, d = e & 63;
            int msrc = mlo + c; if (msrc > QL - 1) msrc = QL - 1;
            rk_s[d * 129 + c] = rk[(size_t)msrc * DMODEL + h * 64 + d];
        }
        if (t < 128) {
            int msrc = mlo + t; if (msrc > QL - 1) msrc = QL - 1;
            brs[t] = br[msrc];
        } else if (t < 192) {
            bks[t - 128] = bk[j0 + (t - 128)];
        }
        __syncthreads();

        float acc[4][4] = {};
        #pragma unroll 4
        for (int d = 0; d < 64; d++) {
            float qv[4], kv[4], rv[7];
            #pragma unroll
            for (int a = 0; a < 4; a++)  qv[a] = q_s[d * 65 + ty * 4 + a];
            #pragma unroll
            for (int b2 = 0; b2 < 4; b2++) kv[b2] = k_s[d * 65 + tx * 4 + b2];
            #pragma unroll
            for (int u = 0; u < 7; u++)  rv[u] = rk_s[d * 129 + cbase - 3 + u];
            #pragma unroll
            for (int a = 0; a < 4; a++)
                #pragma unroll
                for (int b2 = 0; b2 < 4; b2++)
                    acc[a][b2] += qv[a] * (kv[b2] + rv[b2 - a + 3]);
        }

        float brow[7], bcol[4];
        #pragma unroll
        for (int u = 0; u < 7; u++) brow[u] = brs[cbase - 3 + u];
        #pragma unroll
        for (int b2 = 0; b2 < 4; b2++) bcol[b2] = bks[tx * 4 + b2];
        #pragma unroll
        for (int a = 0; a < 4; a++)
            #pragma unroll
            for (int b2 = 0; b2 < 4; b2++) {
                float sc = (acc[a][b2] + bcol[b2] + brow[b2 - a + 3]) * SCALE;
                if (j0 + tx * 4 + b2 > i0 + ty * 4 + a) sc = -1e30f;
                acc[a][b2] = sc;
            }

        #pragma unroll
        for (int a = 0; a < 4; a++) {
            float mx = fmaxf(fmaxf(acc[a][0], acc[a][1]), fmaxf(acc[a][2], acc[a][3]));
            #pragma unroll
            for (int o = 8; o; o >>= 1) mx = fmaxf(mx, __shfl_xor_sync(0xffffffffu, mx, o));
            float mnew = fmaxf(m_run[a], mx);
            float corr = __expf(m_run[a] - mnew);
            float rs = 0.f;
            #pragma unroll
            for (int b2 = 0; b2 < 4; b2++) {
                float p = __expf(acc[a][b2] - mnew);
                acc[a][b2] = p; rs += p;
            }
            #pragma unroll
            for (int o = 8; o; o >>= 1) rs += __shfl_xor_sync(0xffffffffu, rs, o);
            l_run[a] = l_run[a] * corr + rs;
            m_run[a] = mnew;
            #pragma unroll
            for (int b2 = 0; b2 < 4; b2++) o_acc[a][b2] *= corr;
        }

        #pragma unroll
        for (int a = 0; a < 4; a++)
            #pragma unroll
            for (int b2 = 0; b2 < 4; b2++)
                s_s[(ty * 4 + a) * 65 + tx * 4 + b2] = acc[a][b2];
        __syncthreads();
        #pragma unroll 4
        for (int jj = 0; jj < 64; jj++) {
            float pv[4], vv[4];
            #pragma unroll
            for (int a = 0; a < 4; a++)  pv[a] = s_s[(ty * 4 + a) * 65 + jj];
            #pragma unroll
            for (int b2 = 0; b2 < 4; b2++) vv[b2] = v_s[jj * 65 + tx * 4 + b2];
            #pragma unroll
            for (int a = 0; a < 4; a++)
                #pragma unroll
                for (int b2 = 0; b2 < 4; b2++)
                    o_acc[a][b2] += pv[a] * vv[b2];
        }
    }

    #pragma unroll
    for (int a = 0; a < 4; a++) {
        float inv = 1.f / l_run[a];
        #pragma unroll
        for (int b2 = 0; b2 < 4; b2++)
            vec[((size_t)(i0 + ty * 4 + a) * BS + b) * DMODEL + h * 64 + tx * 4 + b2] =
                o_acc[a][b2] * inv;
    }
}

// ---------------- residual + layernorm ----------------
__global__ __launch_bounds__(256) void ln_kernel(const float* __restrict__ w,
                                                 const float* __restrict__ proj,
                                                 const float* __restrict__ g,
                                                 const float* __restrict__ bta,
                                                 float* __restrict__ out) {
    __shared__ float red[8];
    const int row = blockIdx.x;
    const int t = threadIdx.x;
    const size_t base = (size_t)row * DMODEL;
    float x[4];
    float s = 0.f;
    #pragma unroll
    for (int u = 0; u < 4; u++) {
        int c = t + u * 256;
        x[u] = w[base + c] + proj[base + c];
        s += x[u];
    }
    #pragma unroll
    for (int o = 16; o; o >>= 1) s += __shfl_xor_sync(0xffffffffu, s, o);
    if ((t & 31) == 0) red[t >> 5] = s;
    __syncthreads();
    float tot = 0.f;
    #pragma unroll
    for (int i = 0; i < 8; i++) tot += red[i];
    const float mu = tot * (1.f / DMODEL);

    float vs = 0.f;
    #pragma unroll
    for (int u = 0; u < 4; u++) { float dd = x[u] - mu; vs += dd * dd; }
    #pragma unroll
    for (int o = 16; o; o >>= 1) vs += __shfl_xor_sync(0xffffffffu, vs, o);
    __syncthreads();
    if ((t & 31) == 0) red[t >> 5] = vs;
    __syncthreads();
    tot = 0.f;
    #pragma unroll
    for (int i = 0; i < 8; i++) tot += red[i];
    const float rstd = rsqrtf(tot * (1.f / DMODEL) + LNEPS);

    #pragma unroll
    for (int u = 0; u < 4; u++) {
        int c = t + u * 256;
        out[base + c] = (x[u] - mu) * rstd * g[c] + bta[c];
    }
}

// ---------------- launch ----------------
extern "C" void kernel_launch(void* const* d_in, const int* in_sizes, int n_in,
                              void* d_out, int out_size) {
    const float* w    = (const float*)d_in[0];
    const float* r    = (const float*)d_in[1];
    const float* qkvw = (const float*)d_in[3];
    const float* rw   = (const float*)d_in[4];
    const float* ow   = (const float*)d_in[5];
    const float* rrb  = (const float*)d_in[6];
    const float* rwb  = (const float*)d_in[7];
    const float* lng  = (const float*)d_in[8];
    const float* lnb  = (const float*)d_in[9];
    float* out = (float*)d_out;

    float *heads, *rkbuf, *bk, *brv, *vec, *proj, *qkvT, *rwT, *owT;
    cudaGetSymbolAddress((void**)&heads, g_heads);
    cudaGetSymbolAddress((void**)&rkbuf, g_rk);
    cudaGetSymbolAddress((void**)&bk,    g_biask);
    cudaGetSymbolAddress((void**)&brv,   g_biasr);
    cudaGetSymbolAddress((void**)&vec,   g_vec);
    cudaGetSymbolAddress((void**)&proj,  g_proj);
    cudaGetSymbolAddress((void**)&qkvT,  g_qkvT);
    cudaGetSymbolAddress((void**)&rwT,   g_rwT);
    cudaGetSymbolAddress((void**)&owT,   g_owT);

    cudaFuncSetAttribute(attn_kernel, cudaFuncAttributeMaxDynamicSharedMemorySize,
                         ATTN_SMEM_BYTES);

    // 0) transpose weights to [N,K]
    transpose_k<<<dim3(HCOLS / 32, DMODEL / 32), dim3(32, 8)>>>(qkvw, qkvT, DMODEL, HCOLS);
    transpose_k<<<dim3(DMODEL / 32, DMODEL / 32), dim3(32, 8)>>>(rw, rwT, DMODEL, DMODEL);
    transpose_k<<<dim3(DMODEL / 32, DMODEL / 32), dim3(32, 8)>>>(ow, owT, DMODEL, DMODEL);

    // 1) heads = w @ qkv_w
    gemm_tf32<<<dim3(HCOLS / 128, NROWS / 128), 256>>>(w, qkvT, heads, NROWS, HCOLS, DMODEL);
    // 2) r_k = r @ r_w
    gemm_tf32<<<dim3(DMODEL / 128, QL / 128), 256>>>(r, rwT, rkbuf, QL, DMODEL, DMODEL);
    // 3) biases
    bias_k_kernel<<<(BS * NHEAD * QL * 32) / 256, 256>>>(heads, rwb, bk);
    bias_r_kernel<<<(NHEAD * QL * 32) / 256, 256>>>(rkbuf, rrb, brv);
    // 4) attention
    attn_kernel<<<dim3(BS * NHEAD, QL / 64), 256, ATTN_SMEM_BYTES>>>(heads, rkbuf, bk, brv, vec);
    // 5) proj = vec @ o_w
    gemm_tf32<<<dim3(DMODEL / 128, NROWS / 128), 256>>>(vec, owT, proj, NROWS, DMODEL, DMODEL);
    // 6) out = LN(w + proj)
    ln_kernel<<<NROWS, 256>>>(w, proj, lng, lnb, out);
}

// round 4
// speedup vs baseline: 3.0619x; 1.4891x over previous
#include <cuda_runtime.h>
#include <cstdint>
#include <cstddef>

// ---------------- problem constants ----------------
constexpr int QL     = 1024;
constexpr int BS     = 4;
constexpr int DMODEL = 1024;
constexpr int NHEAD  = 16;
constexpr int NROWS  = QL * BS;           // 4096
constexpr int HCOLS  = 3 * NHEAD * 64;    // 3072
constexpr float SCALE = 0.125f;
constexpr float LNEPS = 1e-5f;

// ---------------- scratch ----------------
__device__ float g_heads[(size_t)NROWS * HCOLS];
__device__ float g_rk[(size_t)QL * DMODEL];
__device__ float g_biask[BS * NHEAD * QL];
__device__ float g_biasr[NHEAD * QL];
__device__ float g_vec[(size_t)NROWS * DMODEL];
__device__ float g_proj[(size_t)NROWS * DMODEL];
__device__ float g_qkvT[(size_t)HCOLS * DMODEL];
__device__ float g_rwT[(size_t)DMODEL * DMODEL];
__device__ float g_owT[(size_t)DMODEL * DMODEL];
__device__ float g_bd[(size_t)64 * 1024 * 1024];   // G[bh][i][m] band scores, 256MB

__device__ __forceinline__ float tf32r(float x) {
    float y;
    asm("cvt.rna.tf32.f32 %0, %1;" : "=f"(y) : "f"(x));
    return y;
}
__device__ __forceinline__ void mma_tf32(float* d, const uint32_t* a, const uint32_t* b) {
    asm volatile(
        "mma.sync.aligned.m16n8k8.row.col.f32.tf32.tf32.f32 "
        "{%0,%1,%2,%3}, {%4,%5,%6,%7}, {%8,%9}, {%0,%1,%2,%3};\n"
        : "+f"(d[0]), "+f"(d[1]), "+f"(d[2]), "+f"(d[3])
        : "r"(a[0]), "r"(a[1]), "r"(a[2]), "r"(a[3]), "r"(b[0]), "r"(b[1]));
}

// ---------------- weight transpose: out[n][k] = in[k][n] ----------------
__global__ __launch_bounds__(256) void transpose_k(const float* __restrict__ in,
                                                   float* __restrict__ out,
                                                   int K, int N) {
    __shared__ float t[32][33];
    int n0 = blockIdx.x * 32, k0 = blockIdx.y * 32;
    int tx = threadIdx.x, ty = threadIdx.y;
    #pragma unroll
    for (int i = 0; i < 32; i += 8)
        t[ty + i][tx] = in[(size_t)(k0 + ty + i) * N + n0 + tx];
    __syncthreads();
    #pragma unroll
    for (int i = 0; i < 32; i += 8)
        out[(size_t)(n0 + ty + i) * K + k0 + tx] = t[tx][ty + i];
}

// ---------------- mma.sync tf32 GEMM: C[M,N] = A[M,K] @ BT[N,K]^T ----------------
constexpr int KC = 32;
constexpr int SM_PITCH = 36;

__global__ __launch_bounds__(256)
void gemm_tf32(const float* __restrict__ A, const float* __restrict__ BT,
               float* __restrict__ C, int M, int N, int K) {
    __shared__ float a_s[128 * SM_PITCH];
    __shared__ float b_s[128 * SM_PITCH];

    const int t = threadIdx.x;
    const int wid = t >> 5, lane = t & 31;
    const int wr = wid >> 2, wc = wid & 3;
    const int qrow = lane >> 2, qcol = lane & 3;
    const int row0 = blockIdx.y * 128, col0 = blockIdx.x * 128;

    float acc[4][4][4] = {};

    for (int k0 = 0; k0 < K; k0 += KC) {
        __syncthreads();
        #pragma unroll
        for (int i = 0; i < 4; i++) {
            int idx = t + i * 256;
            int rr = idx >> 3, kq = (idx & 7) * 4;
            float4 va = *(const float4*)&A[(size_t)(row0 + rr) * K + k0 + kq];
            va.x = tf32r(va.x); va.y = tf32r(va.y); va.z = tf32r(va.z); va.w = tf32r(va.w);
            *(float4*)&a_s[rr * SM_PITCH + kq] = va;
            float4 vb = *(const float4*)&BT[(size_t)(col0 + rr) * K + k0 + kq];
            vb.x = tf32r(vb.x); vb.y = tf32r(vb.y); vb.z = tf32r(vb.z); vb.w = tf32r(vb.w);
            *(float4*)&b_s[rr * SM_PITCH + kq] = vb;
        }
        __syncthreads();

        #pragma unroll
        for (int ks = 0; ks < KC / 8; ks++) {
            const int kk = ks * 8;
            uint32_t af[4][4], bf[4][2];
            #pragma unroll
            for (int mt = 0; mt < 4; mt++) {
                const int r0 = wr * 64 + mt * 16 + qrow;
                af[mt][0] = __float_as_uint(a_s[r0 * SM_PITCH + kk + qcol]);
                af[mt][1] = __float_as_uint(a_s[(r0 + 8) * SM_PITCH + kk + qcol]);
                af[mt][2] = __float_as_uint(a_s[r0 * SM_PITCH + kk + qcol + 4]);
                af[mt][3] = __float_as_uint(a_s[(r0 + 8) * SM_PITCH + kk + qcol + 4]);
            }
            #pragma unroll
            for (int nt = 0; nt < 4; nt++) {
                const int n0 = wc * 32 + nt * 8 + qrow;
                bf[nt][0] = __float_as_uint(b_s[n0 * SM_PITCH + kk + qcol]);
                bf[nt][1] = __float_as_uint(b_s[n0 * SM_PITCH + kk + qcol + 4]);
            }
            #pragma unroll
            for (int mt = 0; mt < 4; mt++)
                #pragma unroll
                for (int nt = 0; nt < 4; nt++)
                    mma_tf32(acc[mt][nt], af[mt], bf[nt]);
        }
    }

    #pragma unroll
    for (int mt = 0; mt < 4; mt++) {
        const int row = row0 + wr * 64 + mt * 16 + qrow;
        #pragma unroll
        for (int nt = 0; nt < 4; nt++) {
            const int col = col0 + wc * 32 + nt * 8 + qcol * 2;
            *(float2*)&C[(size_t)row * N + col] = make_float2(acc[mt][nt][0], acc[mt][nt][1]);
            *(float2*)&C[(size_t)(row + 8) * N + col] = make_float2(acc[mt][nt][2], acc[mt][nt][3]);
        }
    }
}

// ---------------- BD band GEMM: g_bd[bh][i][m] = q_i . rk[m] + biasr[h][m] ----------------
// Only the half m >= 1023 - i is ever read -> skip tiles with It+Mt < 7.
__global__ __launch_bounds__(256)
void gemm_bd(const float* __restrict__ heads, const float* __restrict__ rkb,
             const float* __restrict__ brv, float* __restrict__ gbd) {
    const int It = blockIdx.y, Mt = blockIdx.x;
    if (It + Mt < 7) return;
    const int bh = blockIdx.z, b = bh >> 4, h = bh & 15;

    __shared__ float a_s[128 * SM_PITCH];
    __shared__ float b_s[128 * SM_PITCH];

    const int t = threadIdx.x;
    const int wid = t >> 5, lane = t & 31;
    const int wr = wid >> 2, wc = wid & 3;
    const int qrow = lane >> 2, qcol = lane & 3;
    const int row0 = It * 128, col0 = Mt * 128;

    float acc[4][4][4] = {};

    #pragma unroll
    for (int k0 = 0; k0 < 64; k0 += KC) {
        __syncthreads();
        #pragma unroll
        for (int i = 0; i < 4; i++) {
            int idx = t + i * 256;
            int rr = idx >> 3, kq = (idx & 7) * 4;
            float4 va = *(const float4*)&heads[((size_t)(row0 + rr) * BS + b) * HCOLS +
                                               h * 64 + k0 + kq];
            va.x = tf32r(va.x); va.y = tf32r(va.y); va.z = tf32r(va.z); va.w = tf32r(va.w);
            *(float4*)&a_s[rr * SM_PITCH + kq] = va;
            float4 vb = *(const float4*)&rkb[(size_t)(col0 + rr) * DMODEL + h * 64 + k0 + kq];
            vb.x = tf32r(vb.x); vb.y = tf32r(vb.y); vb.z = tf32r(vb.z); vb.w = tf32r(vb.w);
            *(float4*)&b_s[rr * SM_PITCH + kq] = vb;
        }
        __syncthreads();

        #pragma unroll
        for (int ks = 0; ks < KC / 8; ks++) {
            const int kk = ks * 8;
            uint32_t af[4][4], bf[4][2];
            #pragma unroll
            for (int mt = 0; mt < 4; mt++) {
                const int r0 = wr * 64 + mt * 16 + qrow;
                af[mt][0] = __float_as_uint(a_s[r0 * SM_PITCH + kk + qcol]);
                af[mt][1] = __float_as_uint(a_s[(r0 + 8) * SM_PITCH + kk + qcol]);
                af[mt][2] = __float_as_uint(a_s[r0 * SM_PITCH + kk + qcol + 4]);
                af[mt][3] = __float_as_uint(a_s[(r0 + 8) * SM_PITCH + kk + qcol + 4]);
            }
            #pragma unroll
            for (int nt = 0; nt < 4; nt++) {
                const int n0 = wc * 32 + nt * 8 + qrow;
                bf[nt][0] = __float_as_uint(b_s[n0 * SM_PITCH + kk + qcol]);
                bf[nt][1] = __float_as_uint(b_s[n0 * SM_PITCH + kk + qcol + 4]);
            }
            #pragma unroll
            for (int mt = 0; mt < 4; mt++)
                #pragma unroll
                for (int nt = 0; nt < 4; nt++)
                    mma_tf32(acc[mt][nt], af[mt], bf[nt]);
        }
    }

    float* gout = gbd + ((size_t)bh << 20);
    const float* br = brv + h * QL;
    #pragma unroll
    for (int mt = 0; mt < 4; mt++) {
        const int row = row0 + wr * 64 + mt * 16 + qrow;
        #pragma unroll
        for (int nt = 0; nt < 4; nt++) {
            const int col = col0 + wc * 32 + nt * 8 + qcol * 2;
            *(float2*)&gout[(size_t)row * 1024 + col] =
                make_float2(acc[mt][nt][0] + br[col], acc[mt][nt][1] + br[col + 1]);
            *(float2*)&gout[(size_t)(row + 8) * 1024 + col] =
                make_float2(acc[mt][nt][2] + br[col], acc[mt][nt][3] + br[col + 1]);
        }
    }
}

// ---------------- bias precompute ----------------
__global__ __launch_bounds__(256) void bias_k_kernel(const float* __restrict__ heads,
                                                     const float* __restrict__ rwb,
                                                     float* __restrict__ bk) {
    int gt = blockIdx.x * 256 + threadIdx.x;
    int wi = gt >> 5, lane = gt & 31;
    int j = wi & (QL - 1);
    int bh = wi >> 10;
    int b = bh >> 4, h = bh & 15;
    const float* kp = heads + ((size_t)j * BS + b) * HCOLS + 1024 + h * 64;
    const float* wp = rwb + h * 64;
    float s = kp[lane] * wp[lane] + kp[lane + 32] * wp[lane + 32];
    #pragma unroll
    for (int o = 16; o; o >>= 1) s += __shfl_xor_sync(0xffffffffu, s, o);
    if (lane == 0) bk[wi] = s;
}
__global__ __launch_bounds__(256) void bias_r_kernel(const float* __restrict__ rk,
                                                     const float* __restrict__ rrb,
                                                     float* __restrict__ brv) {
    int gt = blockIdx.x * 256 + threadIdx.x;
    int wi = gt >> 5, lane = gt & 31;
    int m = wi & (QL - 1);
    int h = wi >> 10;
    const float* rp = rk + (size_t)m * DMODEL + h * 64;
    const float* wp = rrb + h * 64;
    float s = rp[lane] * wp[lane] + rp[lane + 32] * wp[lane + 32];
    #pragma unroll
    for (int o = 16; o; o >>= 1) s += __shfl_xor_sync(0xffffffffu, s, o);
    if (lane == 0) brv[wi] = s;
}

// ---------------- tensor-core flash attention ----------------
// CTA: 256 threads / 8 warps; 128-row Q tile, 64-col KV tiles; warp = 16 rows.
constexpr int QP = 68;   // pitch for q_s/k_s/p_s (== 4 mod 32 -> conflict-free frag LDS)
constexpr int VP = 72;   // pitch for v_s        (== 8 mod 32)
constexpr int ATTN2_FLOATS = 128 * QP + 64 * QP + 64 * VP + 128 * QP + 64;
constexpr int ATTN2_BYTES  = ATTN2_FLOATS * 4;   // 105728

__global__ __launch_bounds__(256)
void attn2(const float* __restrict__ heads, const float* __restrict__ biask,
           const float* __restrict__ gbd, float* __restrict__ vec) {
    extern __shared__ float sm[];
    float* q_s = sm;                  // [128][QP]
    float* k_s = q_s + 128 * QP;      // [64][QP]
    float* v_s = k_s + 64 * QP;       // [64][VP]
    float* p_s = v_s + 64 * VP;       // [128][QP]
    float* bks = p_s + 128 * QP;      // [64]

    const int bh = blockIdx.x, b = bh >> 4, h = bh & 15;
    const int ib = (int)gridDim.y - 1 - (int)blockIdx.y;  // long blocks first
    const int i0 = ib * 128;
    const int t = threadIdx.x, wid = t >> 5, lane = t & 31;
    const int qr = lane >> 2, qc = lane & 3;
    const int rbase = wid * 16 + qr;

    for (int e = t; e < 128 * 64; e += 256) {
        int ii = e >> 6, d = e & 63;
        q_s[ii * QP + d] = tf32r(heads[((size_t)(i0 + ii) * BS + b) * HCOLS + h * 64 + d]);
    }

    float oacc[8][4] = {};
    float m_run[2] = {-1e30f, -1e30f}, l_run[2] = {0.f, 0.f};
    const float* bk = biask + (size_t)(b * NHEAD + h) * QL;
    const size_t gbase = (size_t)bh << 20;

    const int njt = 2 * ib + 2;
    for (int jt = 0; jt < njt; jt++) {
        const int j0 = jt * 64;
        __syncthreads();
        for (int e = t; e < 64 * 64; e += 256) {
            int jj = e >> 6, d = e & 63;
            size_t base = ((size_t)(j0 + jj) * BS + b) * HCOLS + h * 64 + d;
            k_s[jj * QP + d] = tf32r(heads[base + 1024]);
            v_s[jj * VP + d] = tf32r(heads[base + 2048]);
        }
        if (t < 64) bks[t] = bk[j0 + t];
        __syncthreads();

        // ---- S = Q K^T ----
        float sacc[8][4] = {};
        #pragma unroll
        for (int ks = 0; ks < 8; ks++) {
            const int kk = ks * 8;
            uint32_t af[4];
            af[0] = __float_as_uint(q_s[rbase * QP + kk + qc]);
            af[1] = __float_as_uint(q_s[(rbase + 8) * QP + kk + qc]);
            af[2] = __float_as_uint(q_s[rbase * QP + kk + qc + 4]);
            af[3] = __float_as_uint(q_s[(rbase + 8) * QP + kk + qc + 4]);
            #pragma unroll
            for (int nt = 0; nt < 8; nt++) {
                uint32_t bf[2];
                bf[0] = __float_as_uint(k_s[(nt * 8 + qr) * QP + kk + qc]);
                bf[1] = __float_as_uint(k_s[(nt * 8 + qr) * QP + kk + qc + 4]);
                mma_tf32(sacc[nt], af, bf);
            }
        }

        // ---- + biask + BD band, scale, causal mask ----
        #pragma unroll
        for (int s = 0; s < 2; s++) {
            const int ig = i0 + rbase + s * 8;
            const float* grow = gbd + gbase + (size_t)ig * 1024 + (1023 - ig + j0);
            #pragma unroll
            for (int nt = 0; nt < 8; nt++) {
                #pragma unroll
                for (int r = 0; r < 2; r++) {
                    const int jl = nt * 8 + qc * 2 + r;
                    const int jg = j0 + jl;
                    float v = sacc[nt][s * 2 + r];
                    if (jg <= ig) v = (v + bks[jl] + grow[jl]) * SCALE;
                    else          v = -1e30f;
                    sacc[nt][s * 2 + r] = v;
                }
            }
        }

        // ---- online softmax (row = 4-lane group) ----
        #pragma unroll
        for (int s = 0; s < 2; s++) {
            float mx = -1e30f;
            #pragma unroll
            for (int nt = 0; nt < 8; nt++)
                mx = fmaxf(mx, fmaxf(sacc[nt][s * 2], sacc[nt][s * 2 + 1]));
            mx = fmaxf(mx, __shfl_xor_sync(0xffffffffu, mx, 1));
            mx = fmaxf(mx, __shfl_xor_sync(0xffffffffu, mx, 2));
            float mnew = fmaxf(m_run[s], mx);
            float corr = __expf(m_run[s] - mnew);
            float rs = 0.f;
            #pragma unroll
            for (int nt = 0; nt < 8; nt++) {
                float p0 = __expf(sacc[nt][s * 2] - mnew);
                float p1 = __expf(sacc[nt][s * 2 + 1] - mnew);
                sacc[nt][s * 2] = p0; sacc[nt][s * 2 + 1] = p1;
                rs += p0 + p1;
            }
            rs += __shfl_xor_sync(0xffffffffu, rs, 1);
            rs += __shfl_xor_sync(0xffffffffu, rs, 2);
            l_run[s] = l_run[s] * corr + rs;
            m_run[s] = mnew;
            #pragma unroll
            for (int nt = 0; nt < 8; nt++) {
                oacc[nt][s * 2] *= corr;
                oacc[nt][s * 2 + 1] *= corr;
            }
        }

        // ---- P -> smem (warp-private region) ----
        #pragma unroll
        for (int s = 0; s < 2; s++) {
            #pragma unroll
            for (int nt = 0; nt < 8; nt++) {
                p_s[(rbase + s * 8) * QP + nt * 8 + qc * 2]     = tf32r(sacc[nt][s * 2]);
                p_s[(rbase + s * 8) * QP + nt * 8 + qc * 2 + 1] = tf32r(sacc[nt][s * 2 + 1]);
            }
        }
        __syncwarp();

        // ---- O += P V ----
        #pragma unroll
        for (int ks = 0; ks < 8; ks++) {
            uint32_t af[4];
            af[0] = __float_as_uint(p_s[rbase * QP + ks * 8 + qc]);
            af[1] = __float_as_uint(p_s[(rbase + 8) * QP + ks * 8 + qc]);
            af[2] = __float_as_uint(p_s[rbase * QP + ks * 8 + qc + 4]);
            af[3] = __float_as_uint(p_s[(rbase + 8) * QP + ks * 8 + qc + 4]);
            #pragma unroll
            for (int nt = 0; nt < 8; nt++) {
                uint32_t bf[2];
                bf[0] = __float_as_uint(v_s[(ks * 8 + qc) * VP + nt * 8 + qr]);
                bf[1] = __float_as_uint(v_s[(ks * 8 + qc + 4) * VP + nt * 8 + qr]);
                mma_tf32(oacc[nt], af, bf);
            }
        }
    }

    #pragma unroll
    for (int s = 0; s < 2; s++) {
        const int ig = i0 + rbase + s * 8;
        const float inv = 1.f / l_run[s];
        #pragma unroll
        for (int nt = 0; nt < 8; nt++) {
            float2 o2 = make_float2(oacc[nt][s * 2] * inv, oacc[nt][s * 2 + 1] * inv);
            *(float2*)&vec[((size_t)ig * BS + b) * DMODEL + h * 64 + nt * 8 + qc * 2] = o2;
        }
    }
}

// ---------------- residual + layernorm ----------------
__global__ __launch_bounds__(256) void ln_kernel(const float* __restrict__ w,
                                                 const float* __restrict__ proj,
                                                 const float* __restrict__ g,
                                                 const float* __restrict__ bta,
                                                 float* __restrict__ out) {
    __shared__ float red[8];
    const int row = blockIdx.x;
    const int t = threadIdx.x;
    const size_t base = (size_t)row * DMODEL;
    float x[4];
    float s = 0.f;
    #pragma unroll
    for (int u = 0; u < 4; u++) {
        int c = t + u * 256;
        x[u] = w[base + c] + proj[base + c];
        s += x[u];
    }
    #pragma unroll
    for (int o = 16; o; o >>= 1) s += __shfl_xor_sync(0xffffffffu, s, o);
    if ((t & 31) == 0) red[t >> 5] = s;
    __syncthreads();
    float tot = 0.f;
    #pragma unroll
    for (int i = 0; i < 8; i++) tot += red[i];
    const float mu = tot * (1.f / DMODEL);

    float vs = 0.f;
    #pragma unroll
    for (int u = 0; u < 4; u++) { float dd = x[u] - mu; vs += dd * dd; }
    #pragma unroll
    for (int o = 16; o; o >>= 1) vs += __shfl_xor_sync(0xffffffffu, vs, o);
    __syncthreads();
    if ((t & 31) == 0) red[t >> 5] = vs;
    __syncthreads();
    tot = 0.f;
    #pragma unroll
    for (int i = 0; i < 8; i++) tot += red[i];
    const float rstd = rsqrtf(tot * (1.f / DMODEL) + LNEPS);

    #pragma unroll
    for (int u = 0; u < 4; u++) {
        int c = t + u * 256;
        out[base + c] = (x[u] - mu) * rstd * g[c] + bta[c];
    }
}

// ---------------- launch ----------------
extern "C" void kernel_launch(void* const* d_in, const int* in_sizes, int n_in,
                              void* d_out, int out_size) {
    const float* w    = (const float*)d_in[0];
    const float* r    = (const float*)d_in[1];
    const float* qkvw = (const float*)d_in[3];
    const float* rw   = (const float*)d_in[4];
    const float* ow   = (const float*)d_in[5];
    const float* rrb  = (const float*)d_in[6];
    const float* rwb  = (const float*)d_in[7];
    const float* lng  = (const float*)d_in[8];
    const float* lnb  = (const float*)d_in[9];
    float* out = (float*)d_out;

    float *heads, *rkbuf, *bk, *brv, *vec, *proj, *qkvT, *rwT, *owT, *gbd;
    cudaGetSymbolAddress((void**)&heads, g_heads);
    cudaGetSymbolAddress((void**)&rkbuf, g_rk);
    cudaGetSymbolAddress((void**)&bk,    g_biask);
    cudaGetSymbolAddress((void**)&brv,   g_biasr);
    cudaGetSymbolAddress((void**)&vec,   g_vec);
    cudaGetSymbolAddress((void**)&proj,  g_proj);
    cudaGetSymbolAddress((void**)&qkvT,  g_qkvT);
    cudaGetSymbolAddress((void**)&rwT,   g_rwT);
    cudaGetSymbolAddress((void**)&owT,   g_owT);
    cudaGetSymbolAddress((void**)&gbd,   g_bd);

    cudaFuncSetAttribute(attn2, cudaFuncAttributeMaxDynamicSharedMemorySize, ATTN2_BYTES);

    // 0) transpose weights to [N,K]
    transpose_k<<<dim3(HCOLS / 32, DMODEL / 32), dim3(32, 8)>>>(qkvw, qkvT, DMODEL, HCOLS);
    transpose_k<<<dim3(DMODEL / 32, DMODEL / 32), dim3(32, 8)>>>(rw, rwT, DMODEL, DMODEL);
    transpose_k<<<dim3(DMODEL / 32, DMODEL / 32), dim3(32, 8)>>>(ow, owT, DMODEL, DMODEL);

    // 1) heads = w @ qkv_w ; r_k = r @ r_w
    gemm_tf32<<<dim3(HCOLS / 128, NROWS / 128), 256>>>(w, qkvT, heads, NROWS, HCOLS, DMODEL);
    gemm_tf32<<<dim3(DMODEL / 128, QL / 128), 256>>>(r, rwT, rkbuf, QL, DMODEL, DMODEL);
    // 2) biases
    bias_k_kernel<<<(BS * NHEAD * QL * 32) / 256, 256>>>(heads, rwb, bk);
    bias_r_kernel<<<(NHEAD * QL * 32) / 256, 256>>>(rkbuf, rrb, brv);
    // 3) BD band: g_bd[bh][i][m] = q_i.rk[m] + biasr[m]
    gemm_bd<<<dim3(8, 8, 64), 256>>>(heads, rkbuf, brv, gbd);
    // 4) tensor-core flash attention
    attn2<<<dim3(BS * NHEAD, QL / 128), 256, ATTN2_BYTES>>>(heads, bk, gbd, vec);
    // 5) proj = vec @ o_w
    gemm_tf32<<<dim3(DMODEL / 128, NROWS / 128), 256>>>(vec, owT, proj, NROWS, DMODEL, DMODEL);
    // 6) out = LN(w + proj)
    ln_kernel<<<NROWS, 256>>>(w, proj, lng, lnb, out);
}

// round 9
// speedup vs baseline: 3.3141x; 1.0824x over previous
#include <cuda_runtime.h>
#include <cstdint>
#include <cstddef>

// ---------------- problem constants ----------------
constexpr int QL     = 1024;
constexpr int BS     = 4;
constexpr int DMODEL = 1024;
constexpr int NHEAD  = 16;
constexpr int NROWS  = QL * BS;           // 4096
constexpr int HCOLS  = 3 * NHEAD * 64;    // 3072
constexpr float SCALE = 0.125f;
constexpr float LNEPS = 1e-5f;

// ---------------- scratch ----------------
__device__ float g_heads[(size_t)NROWS * HCOLS];
__device__ float g_rk[(size_t)QL * DMODEL];
__device__ float g_biask[BS * NHEAD * QL];
__device__ float g_biasr[NHEAD * QL];
__device__ float g_vec[(size_t)NROWS * DMODEL];
__device__ float g_proj[(size_t)NROWS * DMODEL];
__device__ float g_qkvT[(size_t)HCOLS * DMODEL];
__device__ float g_rwT[(size_t)DMODEL * DMODEL];
__device__ float g_owT[(size_t)DMODEL * DMODEL];
__device__ float g_bd[(size_t)64 * 1024 * 1024];   // G[bh][i][m] band scores
__device__ float g_wr[(size_t)NROWS * DMODEL];     // tf32-rounded w
__device__ float g_rr[(size_t)QL * DMODEL];        // tf32-rounded r

__device__ __forceinline__ float tf32r(float x) {
    float y;
    asm("cvt.rna.tf32.f32 %0, %1;" : "=f"(y) : "f"(x));
    return y;
}
__device__ __forceinline__ void mma_tf32(float* d, const uint32_t* a, const uint32_t* b) {
    asm volatile(
        "mma.sync.aligned.m16n8k8.row.col.f32.tf32.tf32.f32 "
        "{%0,%1,%2,%3}, {%4,%5,%6,%7}, {%8,%9}, {%0,%1,%2,%3};\n"
        : "+f"(d[0]), "+f"(d[1]), "+f"(d[2]), "+f"(d[3])
        : "r"(a[0]), "r"(a[1]), "r"(a[2]), "r"(a[3]), "r"(b[0]), "r"(b[1]));
}
__device__ __forceinline__ void cp16(uint32_t saddr, const void* g) {
    asm volatile("cp.async.cg.shared.global [%0], [%1], 16;" :: "r"(saddr), "l"(g));
}
#define CP_COMMIT() asm volatile("cp.async.commit_group;" ::: "memory")
#define CP_WAIT1()  asm volatile("cp.async.wait_group 1;" ::: "memory")
#define CP_WAIT0()  asm volatile("cp.async.wait_group 0;" ::: "memory")

// ---------------- tf32 round-copy ----------------
__global__ __launch_bounds__(256) void round_copy(const float4* __restrict__ in,
                                                  float4* __restrict__ out, int n4) {
    int i = blockIdx.x * 256 + threadIdx.x;
    if (i < n4) {
        float4 v = in[i];
        v.x = tf32r(v.x); v.y = tf32r(v.y); v.z = tf32r(v.z); v.w = tf32r(v.w);
        out[i] = v;
    }
}

// ---------------- weight transpose + tf32 round: out[n][k] = tf32(in[k][n]) ----------------
__global__ __launch_bounds__(256) void transpose_k(const float* __restrict__ in,
                                                   float* __restrict__ out,
                                                   int K, int N) {
    __shared__ float t[32][33];
    int n0 = blockIdx.x * 32, k0 = blockIdx.y * 32;
    int tx = threadIdx.x, ty = threadIdx.y;
    #pragma unroll
    for (int i = 0; i < 32; i += 8)
        t[ty + i][tx] = in[(size_t)(k0 + ty + i) * N + n0 + tx];
    __syncthreads();
    #pragma unroll
    for (int i = 0; i < 32; i += 8)
        out[(size_t)(n0 + ty + i) * K + k0 + tx] = tf32r(t[tx][ty + i]);
}

// ---------------- cp.async double-buffered tf32 GEMM: C = A[M,K] @ BT[N,K]^T ----------------
// Inputs MUST be tf32-pre-rounded. CTA 128x128, 8 warps 2x4, warp 64x32, K-chunk 32.
constexpr int KC = 32;
constexpr int SM_PITCH = 36;
constexpr int GSTG = 128 * SM_PITCH;           // floats per stage per operand
constexpr int GEMM_SMEM = 2 * 2 * GSTG * 4;    // 73728 bytes

__global__ __launch_bounds__(256)
void gemm_tf32(const float* __restrict__ A, const float* __restrict__ BT,
               float* __restrict__ C, int M, int N, int K) {
    extern __shared__ float smx[];
    float* a_s = smx;                 // [2][GSTG]
    float* b_s = smx + 2 * GSTG;      // [2][GSTG]
    const uint32_t a_sb = (uint32_t)__cvta_generic_to_shared(a_s);
    const uint32_t b_sb = (uint32_t)__cvta_generic_to_shared(b_s);

    const int t = threadIdx.x;
    const int wid = t >> 5, lane = t & 31;
    const int wr = wid >> 2, wc = wid & 3;
    const int qrow = lane >> 2, qcol = lane & 3;
    const int row0 = blockIdx.y * 128, col0 = blockIdx.x * 128;

    const int lr = t >> 3;             // 0..31
    const int kq = (t & 7) * 4;

    float acc[4][4][4] = {};

    auto load_chunk = [&](int c, int s) {
        const int k0 = c * KC;
        #pragma unroll
        for (int i = 0; i < 4; i++) {
            const int r2 = lr + i * 32;
            const uint32_t soff = (uint32_t)(s * GSTG + r2 * SM_PITCH + kq) * 4;
            cp16(a_sb + soff, &A[(size_t)(row0 + r2) * K + k0 + kq]);
            cp16(b_sb + soff, &BT[(size_t)(col0 + r2) * K + k0 + kq]);
        }
        CP_COMMIT();
    };

    const int NC = K / KC;
    load_chunk(0, 0);

    for (int c = 0; c < NC; c++) {
        const int s = c & 1;
        if (c + 1 < NC) { load_chunk(c + 1, s ^ 1); CP_WAIT1(); }
        else            { CP_WAIT0(); }
        __syncthreads();

        const float* av = a_s + s * GSTG;
        const float* bv = b_s + s * GSTG;
        #pragma unroll
        for (int ks = 0; ks < KC / 8; ks++) {
            const int kk = ks * 8;
            uint32_t af[4][4], bf[4][2];
            #pragma unroll
            for (int mt = 0; mt < 4; mt++) {
                const int r0 = wr * 64 + mt * 16 + qrow;
                af[mt][0] = __float_as_uint(av[r0 * SM_PITCH + kk + qcol]);
                af[mt][1] = __float_as_uint(av[(r0 + 8) * SM_PITCH + kk + qcol]);
                af[mt][2] = __float_as_uint(av[r0 * SM_PITCH + kk + qcol + 4]);
                af[mt][3] = __float_as_uint(av[(r0 + 8) * SM_PITCH + kk + qcol + 4]);
            }
            #pragma unroll
            for (int nt = 0; nt < 4; nt++) {
                const int n0 = wc * 32 + nt * 8 + qrow;
                bf[nt][0] = __float_as_uint(bv[n0 * SM_PITCH + kk + qcol]);
                bf[nt][1] = __float_as_uint(bv[n0 * SM_PITCH + kk + qcol + 4]);
            }
            #pragma unroll
            for (int mt = 0; mt < 4; mt++)
                #pragma unroll
                for (int nt = 0; nt < 4; nt++)
                    mma_tf32(acc[mt][nt], af[mt], bf[nt]);
        }
        __syncthreads();
    }

    #pragma unroll
    for (int mt = 0; mt < 4; mt++) {
        const int row = row0 + wr * 64 + mt * 16 + qrow;
        #pragma unroll
        for (int nt = 0; nt < 4; nt++) {
            const int col = col0 + wc * 32 + nt * 8 + qcol * 2;
            *(float2*)&C[(size_t)row * N + col] = make_float2(acc[mt][nt][0], acc[mt][nt][1]);
            *(float2*)&C[(size_t)(row + 8) * N + col] = make_float2(acc[mt][nt][2], acc[mt][nt][3]);
        }
    }
}

// ---------------- BD band GEMM: g_bd[bh][i][m] = q_i . rk[m] + biasr[h][m] ----------------
__global__ __launch_bounds__(256)
void gemm_bd(const float* __restrict__ heads, const float* __restrict__ rkb,
             const float* __restrict__ brv, float* __restrict__ gbd) {
    const int It = blockIdx.y, Mt = blockIdx.x;
    if (It + Mt < 7) return;
    const int bh = blockIdx.z, b = bh >> 4, h = bh & 15;

    __shared__ float a_s[128 * SM_PITCH];
    __shared__ float b_s[128 * SM_PITCH];

    const int t = threadIdx.x;
    const int wid = t >> 5, lane = t & 31;
    const int wr = wid >> 2, wc = wid & 3;
    const int qrow = lane >> 2, qcol = lane & 3;
    const int row0 = It * 128, col0 = Mt * 128;

    float acc[4][4][4] = {};

    #pragma unroll
    for (int k0 = 0; k0 < 64; k0 += KC) {
        __syncthreads();
        #pragma unroll
        for (int i = 0; i < 4; i++) {
            int idx = t + i * 256;
            int rr = idx >> 3, kqq = (idx & 7) * 4;
            float4 va = *(const float4*)&heads[((size_t)(row0 + rr) * BS + b) * HCOLS +
                                               h * 64 + k0 + kqq];
            va.x = tf32r(va.x); va.y = tf32r(va.y); va.z = tf32r(va.z); va.w = tf32r(va.w);
            *(float4*)&a_s[rr * SM_PITCH + kqq] = va;
            float4 vb = *(const float4*)&rkb[(size_t)(col0 + rr) * DMODEL + h * 64 + k0 + kqq];
            vb.x = tf32r(vb.x); vb.y = tf32r(vb.y); vb.z = tf32r(vb.z); vb.w = tf32r(vb.w);
            *(float4*)&b_s[rr * SM_PITCH + kqq] = vb;
        }
        __syncthreads();

        #pragma unroll
        for (int ks = 0; ks < KC / 8; ks++) {
            const int kk = ks * 8;
            uint32_t af[4][4], bf[4][2];
            #pragma unroll
            for (int mt = 0; mt < 4; mt++) {
                const int r0 = wr * 64 + mt * 16 + qrow;
                af[mt][0] = __float_as_uint(a_s[r0 * SM_PITCH + kk + qcol]);
                af[mt][1] = __float_as_uint(a_s[(r0 + 8) * SM_PITCH + kk + qcol]);
                af[mt][2] = __float_as_uint(a_s[r0 * SM_PITCH + kk + qcol + 4]);
                af[mt][3] = __float_as_uint(a_s[(r0 + 8) * SM_PITCH + kk + qcol + 4]);
            }
            #pragma unroll
            for (int nt = 0; nt < 4; nt++) {
                const int n0 = wc * 32 + nt * 8 + qrow;
                bf[nt][0] = __float_as_uint(b_s[n0 * SM_PITCH + kk + qcol]);
                bf[nt][1] = __float_as_uint(b_s[n0 * SM_PITCH + kk + qcol + 4]);
            }
            #pragma unroll
            for (int mt = 0; mt < 4; mt++)
                #pragma unroll
                for (int nt = 0; nt < 4; nt++)
                    mma_tf32(acc[mt][nt], af[mt], bf[nt]);
        }
    }

    float* gout = gbd + ((size_t)bh << 20);
    const float* br = brv + h * QL;
    #pragma unroll
    for (int mt = 0; mt < 4; mt++) {
        const int row = row0 + wr * 64 + mt * 16 + qrow;
        #pragma unroll
        for (int nt = 0; nt < 4; nt++) {
            const int col = col0 + wc * 32 + nt * 8 + qcol * 2;
            *(float2*)&gout[(size_t)row * 1024 + col] =
                make_float2(acc[mt][nt][0] + br[col], acc[mt][nt][1] + br[col + 1]);
            *(float2*)&gout[(size_t)(row + 8) * 1024 + col] =
                make_float2(acc[mt][nt][2] + br[col], acc[mt][nt][3] + br[col + 1]);
        }
    }
}

// ---------------- bias precompute ----------------
__global__ __launch_bounds__(256) void bias_k_kernel(const float* __restrict__ heads,
                                                     const float* __restrict__ rwb,
                                                     float* __restrict__ bk) {
    int gt = blockIdx.x * 256 + threadIdx.x;
    int wi = gt >> 5, lane = gt & 31;
    int j = wi & (QL - 1);
    int bh = wi >> 10;
    int b = bh >> 4, h = bh & 15;
    const float* kp = heads + ((size_t)j * BS + b) * HCOLS + 1024 + h * 64;
    const float* wp = rwb + h * 64;
    float s = kp[lane] * wp[lane] + kp[lane + 32] * wp[lane + 32];
    #pragma unroll
    for (int o = 16; o; o >>= 1) s += __shfl_xor_sync(0xffffffffu, s, o);
    if (lane == 0) bk[wi] = s;
}
__global__ __launch_bounds__(256) void bias_r_kernel(const float* __restrict__ rk,
                                                     const float* __restrict__ rrb,
                                                     float* __restrict__ brv) {
    int gt = blockIdx.x * 256 + threadIdx.x;
    int wi = gt >> 5, lane = gt & 31;
    int m = wi & (QL - 1);
    int h = wi >> 10;
    const float* rp = rk + (size_t)m * DMODEL + h * 64;
    const float* wp = rrb + h * 64;
    float s = rp[lane] * wp[lane] + rp[lane + 32] * wp[lane + 32];
    #pragma unroll
    for (int o = 16; o; o >>= 1) s += __shfl_xor_sync(0xffffffffu, s, o);
    if (lane == 0) brv[wi] = s;
}

// ---------------- tensor-core flash attention ----------------
constexpr int QP = 68;
constexpr int VP = 72;
constexpr int ATTN2_FLOATS = 128 * QP + 64 * QP + 64 * VP + 128 * QP + 64;
constexpr int ATTN2_BYTES  = ATTN2_FLOATS * 4;

__global__ __launch_bounds__(256)
void attn2(const float* __restrict__ heads, const float* __restrict__ biask,
           const float* __restrict__ gbd, float* __restrict__ vec) {
    extern __shared__ float sm[];
    float* q_s = sm;
    float* k_s = q_s + 128 * QP;
    float* v_s = k_s + 64 * QP;
    float* p_s = v_s + 64 * VP;
    float* bks = p_s + 128 * QP;

    const int bh = blockIdx.x, b = bh >> 4, h = bh & 15;
    const int ib = (int)gridDim.y - 1 - (int)blockIdx.y;
    const int i0 = ib * 128;
    const int t = threadIdx.x, wid = t >> 5, lane = t & 31;
    const int qr = lane >> 2, qc = lane & 3;
    const int rbase = wid * 16 + qr;

    for (int e = t; e < 128 * 64; e += 256) {
        int ii = e >> 6, d = e & 63;
        q_s[ii * QP + d] = tf32r(heads[((size_t)(i0 + ii) * BS + b) * HCOLS + h * 64 + d]);
    }

    float oacc[8][4] = {};
    float m_run[2] = {-1e30f, -1e30f}, l_run[2] = {0.f, 0.f};
    const float* bk = biask + (size_t)(b * NHEAD + h) * QL;
    const size_t gbase = (size_t)bh << 20;

    const int njt = 2 * ib + 2;
    for (int jt = 0; jt < njt; jt++) {
        const int j0 = jt * 64;
        __syncthreads();
        for (int e = t; e < 64 * 64; e += 256) {
            int jj = e >> 6, d = e & 63;
            size_t base = ((size_t)(j0 + jj) * BS + b) * HCOLS + h * 64 + d;
            k_s[jj * QP + d] = tf32r(heads[base + 1024]);
            v_s[jj * VP + d] = tf32r(heads[base + 2048]);
        }
        if (t < 64) bks[t] = bk[j0 + t];
        __syncthreads();

        float sacc[8][4] = {};
        #pragma unroll
        for (int ks = 0; ks < 8; ks++) {
            const int kk = ks * 8;
            uint32_t af[4];
            af[0] = __float_as_uint(q_s[rbase * QP + kk + qc]);
            af[1] = __float_as_uint(q_s[(rbase + 8) * QP + kk + qc]);
            af[2] = __float_as_uint(q_s[rbase * QP + kk + qc + 4]);
            af[3] = __float_as_uint(q_s[(rbase + 8) * QP + kk + qc + 4]);
            #pragma unroll
            for (int nt = 0; nt < 8; nt++) {
                uint32_t bf[2];
                bf[0] = __float_as_uint(k_s[(nt * 8 + qr) * QP + kk + qc]);
                bf[1] = __float_as_uint(k_s[(nt * 8 + qr) * QP + kk + qc + 4]);
                mma_tf32(sacc[nt], af, bf);
            }
        }

        #pragma unroll
        for (int s = 0; s < 2; s++) {
            const int ig = i0 + rbase + s * 8;
            const float* grow = gbd + gbase + (size_t)ig * 1024 + (1023 - ig + j0);
            #pragma unroll
            for (int nt = 0; nt < 8; nt++) {
                #pragma unroll
                for (int r = 0; r < 2; r++) {
                    const int jl = nt * 8 + qc * 2 + r;
                    const int jg = j0 + jl;
                    float v = sacc[nt][s * 2 + r];
                    if (jg <= ig) v = (v + bks[jl] + grow[jl]) * SCALE;
                    else          v = -1e30f;
                    sacc[nt][s * 2 + r] = v;
                }
            }
        }

        #pragma unroll
        for (int s = 0; s < 2; s++) {
            float mx = -1e30f;
            #pragma unroll
            for (int nt = 0; nt < 8; nt++)
                mx = fmaxf(mx, fmaxf(sacc[nt][s * 2], sacc[nt][s * 2 + 1]));
            mx = fmaxf(mx, __shfl_xor_sync(0xffffffffu, mx, 1));
            mx = fmaxf(mx, __shfl_xor_sync(0xffffffffu, mx, 2));
            float mnew = fmaxf(m_run[s], mx);
            float corr = __expf(m_run[s] - mnew);
            float rs = 0.f;
            #pragma unroll
            for (int nt = 0; nt < 8; nt++) {
                float p0 = __expf(sacc[nt][s * 2] - mnew);
                float p1 = __expf(sacc[nt][s * 2 + 1] - mnew);
                sacc[nt][s * 2] = p0; sacc[nt][s * 2 + 1] = p1;
                rs += p0 + p1;
            }
            rs += __shfl_xor_sync(0xffffffffu, rs, 1);
            rs += __shfl_xor_sync(0xffffffffu, rs, 2);
            l_run[s] = l_run[s] * corr + rs;
            m_run[s] = mnew;
            #pragma unroll
            for (int nt = 0; nt < 8; nt++) {
                oacc[nt][s * 2] *= corr;
                oacc[nt][s * 2 + 1] *= corr;
            }
        }

        #pragma unroll
        for (int s = 0; s < 2; s++) {
            #pragma unroll
            for (int nt = 0; nt < 8; nt++) {
                p_s[(rbase + s * 8) * QP + nt * 8 + qc * 2]     = tf32r(sacc[nt][s * 2]);
                p_s[(rbase + s * 8) * QP + nt * 8 + qc * 2 + 1] = tf32r(sacc[nt][s * 2 + 1]);
            }
        }
        __syncwarp();

        #pragma unroll
        for (int ks = 0; ks < 8; ks++) {
            uint32_t af[4];
            af[0] = __float_as_uint(p_s[rbase * QP + ks * 8 + qc]);
            af[1] = __float_as_uint(p_s[(rbase + 8) * QP + ks * 8 + qc]);
            af[2] = __float_as_uint(p_s[rbase * QP + ks * 8 + qc + 4]);
            af[3] = __float_as_uint(p_s[(rbase + 8) * QP + ks * 8 + qc + 4]);
            #pragma unroll
            for (int nt = 0; nt < 8; nt++) {
                uint32_t bf[2];
                bf[0] = __float_as_uint(v_s[(ks * 8 + qc) * VP + nt * 8 + qr]);
                bf[1] = __float_as_uint(v_s[(ks * 8 + qc + 4) * VP + nt * 8 + qr]);
                mma_tf32(oacc[nt], af, bf);
            }
        }
    }

    #pragma unroll
    for (int s = 0; s < 2; s++) {
        const int ig = i0 + rbase + s * 8;
        const float inv = 1.f / l_run[s];
        #pragma unroll
        for (int nt = 0; nt < 8; nt++) {
            // store tf32-rounded: vec feeds the proj GEMM directly
            float2 o2 = make_float2(tf32r(oacc[nt][s * 2] * inv),
                                    tf32r(oacc[nt][s * 2 + 1] * inv));
            *(float2*)&vec[((size_t)ig * BS + b) * DMODEL + h * 64 + nt * 8 + qc * 2] = o2;
        }
    }
}

// ---------------- residual + layernorm ----------------
__global__ __launch_bounds__(256) void ln_kernel(const float* __restrict__ w,
                                                 const float* __restrict__ proj,
                                                 const float* __restrict__ g,
                                                 const float* __restrict__ bta,
                                                 float* __restrict__ out) {
    __shared__ float red[8];
    const int row = blockIdx.x;
    const int t = threadIdx.x;
    const size_t base = (size_t)row * DMODEL;
    float x[4];
    float s = 0.f;
    #pragma unroll
    for (int u = 0; u < 4; u++) {
        int c = t + u * 256;
        x[u] = w[base + c] + proj[base + c];
        s += x[u];
    }
    #pragma unroll
    for (int o = 16; o; o >>= 1) s += __shfl_xor_sync(0xffffffffu, s, o);
    if ((t & 31) == 0) red[t >> 5] = s;
    __syncthreads();
    float tot = 0.f;
    #pragma unroll
    for (int i = 0; i < 8; i++) tot += red[i];
    const float mu = tot * (1.f / DMODEL);

    float vs = 0.f;
    #pragma unroll
    for (int u = 0; u < 4; u++) { float dd = x[u] - mu; vs += dd * dd; }
    #pragma unroll
    for (int o = 16; o; o >>= 1) vs += __shfl_xor_sync(0xffffffffu, vs, o);
    __syncthreads();
    if ((t & 31) == 0) red[t >> 5] = vs;
    __syncthreads();
    tot = 0.f;
    #pragma unroll
    for (int i = 0; i < 8; i++) tot += red[i];
    const float rstd = rsqrtf(tot * (1.f / DMODEL) + LNEPS);

    #pragma unroll
    for (int u = 0; u < 4; u++) {
        int c = t + u * 256;
        out[base + c] = (x[u] - mu) * rstd * g[c] + bta[c];
    }
}

// ---------------- launch ----------------
extern "C" void kernel_launch(void* const* d_in, const int* in_sizes, int n_in,
                              void* d_out, int out_size) {
    const float* w    = (const float*)d_in[0];
    const float* r    = (const float*)d_in[1];
    const float* qkvw = (const float*)d_in[3];
    const float* rw   = (const float*)d_in[4];
    const float* ow   = (const float*)d_in[5];
    const float* rrb  = (const float*)d_in[6];
    const float* rwb  = (const float*)d_in[7];
    const float* lng  = (const float*)d_in[8];
    const float* lnb  = (const float*)d_in[9];
    float* out = (float*)d_out;

    float *heads, *rkbuf, *bk, *brv, *vec, *proj, *qkvT, *rwT, *owT, *gbd, *wr, *rr;
    cudaGetSymbolAddress((void**)&heads, g_heads);
    cudaGetSymbolAddress((void**)&rkbuf, g_rk);
    cudaGetSymbolAddress((void**)&bk,    g_biask);
    cudaGetSymbolAddress((void**)&brv,   g_biasr);
    cudaGetSymbolAddress((void**)&vec,   g_vec);
    cudaGetSymbolAddress((void**)&proj,  g_proj);
    cudaGetSymbolAddress((void**)&qkvT,  g_qkvT);
    cudaGetSymbolAddress((void**)&rwT,   g_rwT);
    cudaGetSymbolAddress((void**)&owT,   g_owT);
    cudaGetSymbolAddress((void**)&gbd,   g_bd);
    cudaGetSymbolAddress((void**)&wr,    g_wr);
    cudaGetSymbolAddress((void**)&rr,    g_rr);

    cudaFuncSetAttribute(attn2, cudaFuncAttributeMaxDynamicSharedMemorySize, ATTN2_BYTES);
    cudaFuncSetAttribute(gemm_tf32, cudaFuncAttributeMaxDynamicSharedMemorySize, GEMM_SMEM);

    // 0) pre-round A operands; transpose + round weights to [N,K]
    round_copy<<<(NROWS * DMODEL / 4) / 256, 256>>>((const float4*)w, (float4*)wr,
                                                    NROWS * DMODEL / 4);
    round_copy<<<(QL * DMODEL / 4) / 256, 256>>>((const float4*)r, (float4*)rr,
                                                 QL * DMODEL / 4);
    transpose_k<<<dim3(HCOLS / 32, DMODEL / 32), dim3(32, 8)>>>(qkvw, qkvT, DMODEL, HCOLS);
    transpose_k<<<dim3(DMODEL / 32, DMODEL / 32), dim3(32, 8)>>>(rw, rwT, DMODEL, DMODEL);
    transpose_k<<<dim3(DMODEL / 32, DMODEL / 32), dim3(32, 8)>>>(ow, owT, DMODEL, DMODEL);

    // 1) heads = w @ qkv_w ; r_k = r @ r_w
    gemm_tf32<<<dim3(HCOLS / 128, NROWS / 128), 256, GEMM_SMEM>>>(
        wr, qkvT, heads, NROWS, HCOLS, DMODEL);
    gemm_tf32<<<dim3(DMODEL / 128, QL / 128), 256, GEMM_SMEM>>>(
        rr, rwT, rkbuf, QL, DMODEL, DMODEL);
    // 2) biases
    bias_k_kernel<<<(BS * NHEAD * QL * 32) / 256, 256>>>(heads, rwb, bk);
    bias_r_kernel<<<(NHEAD * QL * 32) / 256, 256>>>(rkbuf, rrb, brv);
    // 3) BD band
    gemm_bd<<<dim3(8, 8, 64), 256>>>(heads, rkbuf, brv, gbd);
    // 4) tensor-core flash attention (writes tf32-rounded vec)
    attn2<<<dim3(BS * NHEAD, QL / 128), 256, ATTN2_BYTES>>>(heads, bk, gbd, vec);
    // 5) proj = vec @ o_w
    gemm_tf32<<<dim3(DMODEL / 128, NROWS / 128), 256, GEMM_SMEM>>>(
        vec, owT, proj, NROWS, DMODEL, DMODEL);
    // 6) out = LN(w + proj)
    ln_kernel<<<NROWS, 256>>>(w, proj, lng, lnb, out);
}